// round 2
// baseline (speedup 1.0000x reference)
#include <cuda_runtime.h>
#include <cstdint>

#define DINLINE __device__ __forceinline__

constexpr int T   = 2048;   // tokens
constexpr int H   = 2048;   // hidden
constexpr int NE  = 16;     // experts
constexpr int IE  = 512;    // expert intermediate
constexpr int ISZ = 2048;   // shared intermediate
constexpr int MAXROWS  = 6144;  // 4096 pairs + 16*128 tile padding
constexpr int MAXTILES = 48;

constexpr int BM = 128, BN = 128, BK = 16, PAD = 20;

// ---------------- scratch (device globals; no allocation allowed) ------------
__device__ int   g_counts[NE];
__device__ int   g_off[NE];
__device__ int   g_cursor[NE];
__device__ int   g_tile_expert[MAXTILES];
__device__ int   g_rowtok[MAXROWS];
__device__ float g_roww[MAXROWS];
__device__ int   g_sel[T * 2];
__device__ float g_wk[T * 2];
__device__ int   g_pairslot[T * 2];
__device__ float g_gate[T];
__device__ float g_mid12[(size_t)MAXROWS * 1024];   // expert gate|up raw
__device__ float g_hmid [(size_t)MAXROWS * IE];     // expert swiglu * weight
__device__ float g_outp [(size_t)MAXROWS * H];      // expert partial outputs
__device__ float g_smid [(size_t)T * 2 * ISZ];      // shared gate|up raw
__device__ float g_shmid[(size_t)T * ISZ];          // shared swiglu

// ---------------- small kernels ---------------------------------------------
__global__ void zero_init() {
    int i = blockIdx.x * blockDim.x + threadIdx.x;
    if (i < MAXROWS) { g_rowtok[i] = -1; g_roww[i] = 0.f; }
    if (i < NE) g_counts[i] = 0;
}

// One warp per token: 16 router logits + 1 shared-gate logit.
__global__ void router_k(const float* __restrict__ X,
                         const float* __restrict__ GW,
                         const float* __restrict__ SGW) {
    __shared__ float Ws[17][128];
    int lane = threadIdx.x & 31, warp = threadIdx.x >> 5;
    int t = blockIdx.x * 4 + warp;

    float acc[17];
#pragma unroll
    for (int e = 0; e < 17; e++) acc[e] = 0.f;

    for (int k0 = 0; k0 < H; k0 += 128) {
        __syncthreads();
        for (int j = threadIdx.x; j < 17 * 128; j += 128) {
            int e = j >> 7, kk = j & 127;
            Ws[e][kk] = (e < 16) ? GW[e * H + k0 + kk] : SGW[k0 + kk];
        }
        __syncthreads();
        float xv[4];
#pragma unroll
        for (int i = 0; i < 4; i++) xv[i] = X[(size_t)t * H + k0 + i * 32 + lane];
#pragma unroll
        for (int e = 0; e < 17; e++) {
#pragma unroll
            for (int i = 0; i < 4; i++) acc[e] += xv[i] * Ws[e][i * 32 + lane];
        }
    }
#pragma unroll
    for (int e = 0; e < 17; e++) {
        float v = acc[e];
#pragma unroll
        for (int o = 16; o > 0; o >>= 1) v += __shfl_xor_sync(0xffffffffu, v, o);
        acc[e] = v;
    }
    if (lane == 0) {
        int i1 = 0;
        for (int e = 1; e < 16; e++) if (acc[e] > acc[i1]) i1 = e;
        int i2 = (i1 == 0) ? 1 : 0;
        for (int e = 0; e < 16; e++) if (e != i1 && acc[e] > acc[i2]) i2 = e;
        float m  = acc[i1];
        float e1 = expf(acc[i1] - m), e2 = expf(acc[i2] - m);
        float s  = e1 + e2;
        g_sel[t * 2] = i1;  g_sel[t * 2 + 1] = i2;
        g_wk [t * 2] = e1 / s;  g_wk [t * 2 + 1] = e2 / s;   // softmax denom cancels
        atomicAdd(&g_counts[i1], 1);
        atomicAdd(&g_counts[i2], 1);
        g_gate[t] = 1.f / (1.f + expf(-acc[16]));
    }
}

// Tile-padded exclusive scan over expert counts; tile -> expert table.
__global__ void offsets_k() {
    if (threadIdx.x == 0 && blockIdx.x == 0) {
        int off = 0, tile = 0;
        for (int e = 0; e < NE; e++) {
            g_off[e] = off;
            g_cursor[e] = 0;
            int nt = (g_counts[e] + BM - 1) / BM;
            for (int j = 0; j < nt; j++) g_tile_expert[tile++] = e;
            off += nt * BM;
        }
        for (; tile < MAXTILES; tile++) g_tile_expert[tile] = -1;
    }
}

__global__ void scatter_k() {
    int t = blockIdx.x * blockDim.x + threadIdx.x;
    if (t >= T) return;
#pragma unroll
    for (int k = 0; k < 2; k++) {
        int e   = g_sel[t * 2 + k];
        int pos = atomicAdd(&g_cursor[e], 1);
        int row = g_off[e] + pos;
        g_rowtok[row] = t;
        g_roww[row]   = g_wk[t * 2 + k];
        g_pairslot[t * 2 + k] = row;
    }
}

// ---------------- tf32 MMA GEMM ----------------------------------------------
DINLINE unsigned cvt_tf32(float f) {
    unsigned u;
    asm("cvt.rna.tf32.f32 %0, %1;" : "=r"(u) : "f"(f));
    return u;
}
DINLINE uint4 tf4(float4 v) {
    return make_uint4(cvt_tf32(v.x), cvt_tf32(v.y), cvt_tf32(v.z), cvt_tf32(v.w));
}
DINLINE void mma8(float* c, const unsigned* a, const unsigned* b) {
    asm volatile(
        "mma.sync.aligned.m16n8k8.row.col.f32.tf32.tf32.f32 "
        "{%0,%1,%2,%3}, {%4,%5,%6,%7}, {%8,%9}, {%0,%1,%2,%3};"
        : "+f"(c[0]), "+f"(c[1]), "+f"(c[2]), "+f"(c[3])
        : "r"(a[0]), "r"(a[1]), "r"(a[2]), "r"(a[3]), "r"(b[0]), "r"(b[1]));
}

// MODE 0: expert gate/up  C[row,1024] = Xg[row,H]   * [w1;w3]^T   (gathered rows)
// MODE 1: expert down     C[row,H]    = hmid[row,I] * w2^T
// MODE 2: shared gate/up  C[t,4096]   = X[t,H]      * [wsg;wsu]^T
// MODE 3: shared down     out[t,H]    = gate[t] * (shmid[t,IS] * wsd^T)
template <int MODE>
__global__ void __launch_bounds__(256, 1)
gemm_k(const float* __restrict__ Ain, const float* __restrict__ Wa,
       const float* __restrict__ Wb, float* __restrict__ Out) {
    __shared__ unsigned As[2][BM * PAD];
    __shared__ unsigned Bs[2][BN * PAD];

    int by = blockIdx.y, bx = blockIdx.x;
    int e = 0;
    if (MODE == 0 || MODE == 1) {
        e = g_tile_expert[by];
        if (e < 0) return;
    }
    int m0 = by * BM, n0 = bx * BN;
    int tid = threadIdx.x;
    int arow = tid >> 1, acol = (tid & 1) * 8;

    constexpr int KS = (MODE == 1) ? IE : ((MODE == 3) ? ISZ : H);
    constexpr int ksteps = KS / BK;

    const float* aptr = nullptr;
    if constexpr (MODE == 0) {
        int tok = g_rowtok[m0 + arow];
        if (tok >= 0) aptr = Ain + (size_t)tok * H + acol;
    } else if constexpr (MODE == 1) {
        aptr = g_hmid + (size_t)(m0 + arow) * IE + acol;
    } else if constexpr (MODE == 2) {
        aptr = Ain + (size_t)(m0 + arow) * H + acol;
    } else {
        aptr = g_shmid + (size_t)(m0 + arow) * ISZ + acol;
    }

    int n = n0 + arow;
    const float* bptr;
    if constexpr (MODE == 0)
        bptr = ((n < IE) ? (Wa + ((size_t)e * IE + n) * H)
                         : (Wb + ((size_t)e * IE + (n - IE)) * H)) + acol;
    else if constexpr (MODE == 1)
        bptr = Wa + ((size_t)e * H + n) * IE + acol;
    else if constexpr (MODE == 2)
        bptr = ((n < ISZ) ? (Wa + (size_t)n * H) : (Wb + (size_t)(n - ISZ) * H)) + acol;
    else
        bptr = Wa + (size_t)n * ISZ + acol;

    float acc[4][4][4];
#pragma unroll
    for (int i = 0; i < 4; i++)
#pragma unroll
        for (int j = 0; j < 4; j++)
#pragma unroll
            for (int k = 0; k < 4; k++) acc[i][j][k] = 0.f;

    int wid = tid >> 5, lane = tid & 31;
    int wr = wid >> 2, wc = wid & 3;       // 2 x 4 warp grid, warp tile 64x32
    int gq = lane >> 2, tg = lane & 3;

    unsigned* as_d[2] = { &As[0][arow * PAD + acol], &As[1][arow * PAD + acol] };
    unsigned* bs_d[2] = { &Bs[0][arow * PAD + acol], &Bs[1][arow * PAD + acol] };

    const float4 z4 = make_float4(0.f, 0.f, 0.f, 0.f);
    // stage 0
    {
        float4 a0 = aptr ? *reinterpret_cast<const float4*>(aptr)     : z4;
        float4 a1 = aptr ? *reinterpret_cast<const float4*>(aptr + 4) : z4;
        float4 b0 = *reinterpret_cast<const float4*>(bptr);
        float4 b1 = *reinterpret_cast<const float4*>(bptr + 4);
        *reinterpret_cast<uint4*>(as_d[0])     = tf4(a0);
        *reinterpret_cast<uint4*>(as_d[0] + 4) = tf4(a1);
        *reinterpret_cast<uint4*>(bs_d[0])     = tf4(b0);
        *reinterpret_cast<uint4*>(bs_d[0] + 4) = tf4(b1);
    }
    if (aptr) aptr += BK;
    bptr += BK;
    __syncthreads();

#pragma unroll 1
    for (int kt = 0; kt < ksteps; ++kt) {
        int cur = kt & 1;
        bool pf = (kt + 1) < ksteps;
        float4 a0, a1, b0, b1;
        if (pf) {
            a0 = aptr ? *reinterpret_cast<const float4*>(aptr)     : z4;
            a1 = aptr ? *reinterpret_cast<const float4*>(aptr + 4) : z4;
            b0 = *reinterpret_cast<const float4*>(bptr);
            b1 = *reinterpret_cast<const float4*>(bptr + 4);
            if (aptr) aptr += BK;
            bptr += BK;
        }
        const unsigned* Ab = As[cur];
        const unsigned* Bb = Bs[cur];
#pragma unroll
        for (int kk = 0; kk < 2; ++kk) {
            int kb = kk * 8;
            unsigned af[4][4], bf[4][2];
#pragma unroll
            for (int mi = 0; mi < 4; mi++) {
                int r = wr * 64 + mi * 16 + gq;
                const unsigned* p = Ab + r * PAD + kb + tg;
                af[mi][0] = p[0];
                af[mi][1] = p[8 * PAD];
                af[mi][2] = p[4];
                af[mi][3] = p[8 * PAD + 4];
            }
#pragma unroll
            for (int ni = 0; ni < 4; ni++) {
                int nn = wc * 32 + ni * 8 + gq;
                const unsigned* p = Bb + nn * PAD + kb + tg;
                bf[ni][0] = p[0];
                bf[ni][1] = p[4];
            }
#pragma unroll
            for (int mi = 0; mi < 4; mi++)
#pragma unroll
                for (int ni = 0; ni < 4; ni++) mma8(acc[mi][ni], af[mi], bf[ni]);
        }
        if (pf) {
            unsigned* ad = as_d[cur ^ 1];
            unsigned* bd = bs_d[cur ^ 1];
            *reinterpret_cast<uint4*>(ad)     = tf4(a0);
            *reinterpret_cast<uint4*>(ad + 4) = tf4(a1);
            *reinterpret_cast<uint4*>(bd)     = tf4(b0);
            *reinterpret_cast<uint4*>(bd + 4) = tf4(b1);
        }
        __syncthreads();
    }

    // epilogue
#pragma unroll
    for (int mi = 0; mi < 4; mi++) {
#pragma unroll
        for (int ni = 0; ni < 4; ni++) {
            int r = m0 + wr * 64 + mi * 16 + gq;
            int c = n0 + wc * 32 + ni * 8 + 2 * tg;
            float2 v0 = make_float2(acc[mi][ni][0], acc[mi][ni][1]);
            float2 v1 = make_float2(acc[mi][ni][2], acc[mi][ni][3]);
            if constexpr (MODE == 0) {
                *reinterpret_cast<float2*>(&g_mid12[(size_t)r * 1024 + c])       = v0;
                *reinterpret_cast<float2*>(&g_mid12[(size_t)(r + 8) * 1024 + c]) = v1;
            } else if constexpr (MODE == 1) {
                *reinterpret_cast<float2*>(&g_outp[(size_t)r * H + c])       = v0;
                *reinterpret_cast<float2*>(&g_outp[(size_t)(r + 8) * H + c]) = v1;
            } else if constexpr (MODE == 2) {
                *reinterpret_cast<float2*>(&g_smid[(size_t)r * (2 * ISZ) + c])       = v0;
                *reinterpret_cast<float2*>(&g_smid[(size_t)(r + 8) * (2 * ISZ) + c]) = v1;
            } else {
                float ga0 = g_gate[r], ga1 = g_gate[r + 8];
                v0.x *= ga0; v0.y *= ga0;
                v1.x *= ga1; v1.y *= ga1;
                *reinterpret_cast<float2*>(&Out[(size_t)r * H + c])       = v0;
                *reinterpret_cast<float2*>(&Out[(size_t)(r + 8) * H + c]) = v1;
            }
        }
    }
}

// ---------------- elementwise -------------------------------------------------
__global__ void swiglu_e() {
    size_t idx = (size_t)blockIdx.x * blockDim.x + threadIdx.x;
    if (idx >= (size_t)MAXROWS * IE) return;
    int row = (int)(idx / IE), i = (int)(idx % IE);
    float v = 0.f;
    if (g_rowtok[row] >= 0) {
        float gv = g_mid12[(size_t)row * 1024 + i];
        float uv = g_mid12[(size_t)row * 1024 + 512 + i];
        v = gv / (1.f + expf(-gv)) * uv * g_roww[row];
    }
    g_hmid[idx] = v;
}

__global__ void swiglu_sh() {
    size_t idx = (size_t)blockIdx.x * blockDim.x + threadIdx.x;
    if (idx >= (size_t)T * ISZ) return;
    int t = (int)(idx / ISZ), i = (int)(idx % ISZ);
    float gv = g_smid[(size_t)t * 2 * ISZ + i];
    float uv = g_smid[(size_t)t * 2 * ISZ + ISZ + i];
    g_shmid[idx] = gv / (1.f + expf(-gv)) * uv;
}

__global__ void final_add(float* __restrict__ out) {
    size_t idx = (size_t)blockIdx.x * blockDim.x + threadIdx.x;
    if (idx >= (size_t)T * H) return;
    int t = (int)(idx / H), h = (int)(idx % H);
    int p0 = g_pairslot[t * 2], p1 = g_pairslot[t * 2 + 1];
    out[idx] += g_outp[(size_t)p0 * H + h] + g_outp[(size_t)p1 * H + h];
}

// ---------------- launch ------------------------------------------------------
extern "C" void kernel_launch(void* const* d_in, const int* in_sizes, int n_in,
                              void* d_out, int out_size) {
    (void)in_sizes; (void)n_in; (void)out_size;
    const float* X   = (const float*)d_in[0];
    const float* GW  = (const float*)d_in[1];
    const float* W1  = (const float*)d_in[2];
    const float* W2  = (const float*)d_in[3];
    const float* W3  = (const float*)d_in[4];
    const float* WSG = (const float*)d_in[5];
    const float* WSU = (const float*)d_in[6];
    const float* WSD = (const float*)d_in[7];
    const float* SGW = (const float*)d_in[8];
    float* out = (float*)d_out;

    zero_init<<<(MAXROWS + 255) / 256, 256>>>();
    router_k<<<T / 4, 128>>>(X, GW, SGW);
    offsets_k<<<1, 32>>>();
    scatter_k<<<(T + 255) / 256, 256>>>();

    // routed experts
    gemm_k<0><<<dim3(1024 / BN, MAXTILES), 256>>>(X, W1, W3, nullptr);
    swiglu_e<<<(MAXROWS * IE) / 256, 256>>>();
    gemm_k<1><<<dim3(H / BN, MAXTILES), 256>>>(nullptr, W2, nullptr, nullptr);

    // shared expert (writes base of d_out)
    gemm_k<2><<<dim3((2 * ISZ) / BN, T / BM), 256>>>(X, WSG, WSU, nullptr);
    swiglu_sh<<<(T * ISZ) / 256, 256>>>();
    gemm_k<3><<<dim3(H / BN, T / BM), 256>>>(nullptr, WSD, nullptr, out);

    // out += routed expert contributions (deterministic, no float atomics)
    final_add<<<(T * H) / 256, 256>>>(out);
}